// round 7
// baseline (speedup 1.0000x reference)
#include <cuda_runtime.h>

// LabelLoss: out[b] = sum_{n,c<7} (pred[b,n,c] - gt[b,n,c])^2
// pred, gt: [256, 16384, 8] fp32. Pure HBM-bound streaming reduction.
//
// R7: single kernel, ticket-fused final reduction like R6, but the gpu-scope
// __threadfence (CCTL.IVALL L1-flush per block on sm_103a) is replaced by a
// release atomic on the ticket + acquire loads of the partials. SPLIT=16
// halves ticket events while keeping multi-wave work-stealing.

#define B_DIM       256
#define N_OBJ       16384
#define THREADS     256
#define SPLIT       16                        // chunks per batch row -> grid 4096
#define F4_PER_ROW  (N_OBJ * 2)               // 32768 float4 per batch row
#define F4_PER_BLK  (F4_PER_ROW / SPLIT)      // 2048 float4 per block per stream
#define UNROLL      4

// Partial sums [b][s]: finishing half-warp reads 64B, coalesced, L2-hit.
__device__ float g_partials[B_DIM * SPLIT];
// Ticket counters, one per batch row. Zero-initialized; self-reset each launch.
__device__ unsigned int g_count[B_DIM];

__device__ __forceinline__ unsigned int atom_add_acqrel_gpu(unsigned int* a, unsigned int v) {
    unsigned int r;
    asm volatile("atom.add.acq_rel.gpu.global.u32 %0, [%1], %2;"
                 : "=r"(r) : "l"(a), "r"(v) : "memory");
    return r;
}

__device__ __forceinline__ float ld_acquire_gpu(const float* a) {
    float r;
    asm volatile("ld.acquire.gpu.global.f32 %0, [%1];" : "=f"(r) : "l"(a) : "memory");
    return r;
}

__global__ __launch_bounds__(THREADS, 8)
void label_loss_kernel(const float* __restrict__ pred,
                       const float* __restrict__ gt,
                       float* __restrict__ out) {
    const int b = blockIdx.x;
    const int s = blockIdx.y;

    const float4* __restrict__ p =
        reinterpret_cast<const float4*>(pred) + (size_t)b * F4_PER_ROW + s * F4_PER_BLK;
    const float4* __restrict__ g =
        reinterpret_cast<const float4*>(gt)   + (size_t)b * F4_PER_ROW + s * F4_PER_BLK;

    // float4-index parity for this thread is constant (strides even):
    // odd float4 -> its .w is channel 7 (excluded from loss).
    const float wsel = (threadIdx.x & 1) ? 0.0f : 1.0f;

    float acc = 0.0f;

    // 2048 float4 / (256 threads * 4 unroll) = 2 outer iterations,
    // each with 8 front-batched LDG.128 per thread.
    #pragma unroll 1
    for (int base = 0; base < F4_PER_BLK; base += THREADS * UNROLL) {
        float4 pv[UNROLL], gv[UNROLL];
        #pragma unroll
        for (int u = 0; u < UNROLL; u++) {
            const int idx = base + u * THREADS + threadIdx.x;
            pv[u] = p[idx];
            gv[u] = g[idx];
        }
        #pragma unroll
        for (int u = 0; u < UNROLL; u++) {
            float d0 = pv[u].x - gv[u].x;
            float d1 = pv[u].y - gv[u].y;
            float d2 = pv[u].z - gv[u].z;
            float d3 = (pv[u].w - gv[u].w) * wsel;   // channel 7 masked on odd lanes
            acc += d0*d0 + d1*d1 + d2*d2 + d3*d3;
        }
    }

    // Warp reduction
    #pragma unroll
    for (int off = 16; off > 0; off >>= 1)
        acc += __shfl_xor_sync(0xFFFFFFFFu, acc, off);

    // Cross-warp reduction via shared memory
    __shared__ float warp_sums[THREADS / 32];
    const int lane = threadIdx.x & 31;
    const int wid  = threadIdx.x >> 5;
    if (lane == 0) warp_sums[wid] = acc;
    __syncthreads();

    if (wid == 0) {
        float v = (lane < THREADS / 32) ? warp_sums[lane] : 0.0f;
        #pragma unroll
        for (int off = 4; off > 0; off >>= 1)
            v += __shfl_xor_sync(0xFFFFFFFFu, v, off);

        // Publish partial (plain store), then release-ticket. The release
        // atomic orders the store without a gpu-scope fence / L1 flush.
        unsigned int ticket = 0;
        if (lane == 0) {
            g_partials[b * SPLIT + s] = v;
            ticket = atom_add_acqrel_gpu(&g_count[b], 1u);
        }
        ticket = __shfl_sync(0xFFFFFFFFu, ticket, 0);

        // Last block for this batch row reduces all SPLIT partials.
        if (ticket == SPLIT - 1) {
            float r = (lane < SPLIT)
                    ? ld_acquire_gpu(&g_partials[b * SPLIT + lane]) : 0.0f;
            #pragma unroll
            for (int off = 16; off > 0; off >>= 1)
                r += __shfl_xor_sync(0xFFFFFFFFu, r, off);
            if (lane == 0) {
                out[b] = r;
                g_count[b] = 0;                      // reset for next graph replay
            }
        }
    }
}

extern "C" void kernel_launch(void* const* d_in, const int* in_sizes, int n_in,
                              void* d_out, int out_size) {
    const float* pred = (const float*)d_in[0];
    const float* gt   = (const float*)d_in[1];
    float* out        = (float*)d_out;

    dim3 grid(B_DIM, SPLIT);
    label_loss_kernel<<<grid, THREADS>>>(pred, gt, out);
}

// round 8
// speedup vs baseline: 1.0463x; 1.0463x over previous
#include <cuda_runtime.h>

// LabelLoss: out[b] = sum_{n,c<7} (pred[b,n,c] - gt[b,n,c])^2
// pred, gt: [256, 16384, 8] fp32. Pure HBM-bound streaming reduction.
//
// R8: R6's tied-best fused single-kernel config (SPLIT=32, ticket-based
// last-block reduction), with (a) release-atomic ticket instead of the
// gpu-scope __threadfence (no per-block L1 flush), and (b) read-only
// non-coherent 128-bit loads (LDG.E.128.CONSTANT) for the two streams.

#define B_DIM       256
#define N_OBJ       16384
#define THREADS     256
#define SPLIT       32                        // chunks per batch row -> grid 8192
#define F4_PER_ROW  (N_OBJ * 2)               // 32768 float4 per batch row
#define F4_PER_BLK  (F4_PER_ROW / SPLIT)      // 1024 float4 per block (per stream)
#define UNROLL      4                         // THREADS*UNROLL == F4_PER_BLK

// Partial sums [b][s]: finishing warp reads one 128B line, coalesced, L2-hit.
__device__ float g_partials[B_DIM * SPLIT];
// Ticket counters, one per batch row. Zero-initialized; self-reset each launch.
__device__ unsigned int g_count[B_DIM];

__device__ __forceinline__ float4 ldg_nc_f4(const float4* a) {
    float4 v;
    asm volatile("ld.global.nc.v4.f32 {%0,%1,%2,%3}, [%4];"
                 : "=f"(v.x), "=f"(v.y), "=f"(v.z), "=f"(v.w) : "l"(a));
    return v;
}

__device__ __forceinline__ unsigned int atom_add_release_gpu(unsigned int* a, unsigned int v) {
    unsigned int r;
    asm volatile("atom.add.release.gpu.global.u32 %0, [%1], %2;"
                 : "=r"(r) : "l"(a), "r"(v) : "memory");
    return r;
}

__device__ __forceinline__ float ld_acquire_gpu(const float* a) {
    float r;
    asm volatile("ld.acquire.gpu.global.f32 %0, [%1];" : "=f"(r) : "l"(a) : "memory");
    return r;
}

__global__ __launch_bounds__(THREADS, 8)
void label_loss_kernel(const float* __restrict__ pred,
                       const float* __restrict__ gt,
                       float* __restrict__ out) {
    const int b = blockIdx.x;
    const int s = blockIdx.y;

    const float4* __restrict__ p =
        reinterpret_cast<const float4*>(pred) + (size_t)b * F4_PER_ROW + s * F4_PER_BLK;
    const float4* __restrict__ g =
        reinterpret_cast<const float4*>(gt)   + (size_t)b * F4_PER_ROW + s * F4_PER_BLK;

    // float4-index parity for this thread is constant (strides even):
    // odd float4 -> its .w is channel 7 (excluded from loss).
    const float wsel = (threadIdx.x & 1) ? 0.0f : 1.0f;

    // One fully-unrolled pass: 4 p + 4 g = 8 front-batched LDG.128 per thread.
    float4 pv[UNROLL], gv[UNROLL];
    #pragma unroll
    for (int u = 0; u < UNROLL; u++) {
        const int idx = u * THREADS + threadIdx.x;
        pv[u] = ldg_nc_f4(p + idx);
        gv[u] = ldg_nc_f4(g + idx);
    }

    float acc = 0.0f;
    #pragma unroll
    for (int u = 0; u < UNROLL; u++) {
        float d0 = pv[u].x - gv[u].x;
        float d1 = pv[u].y - gv[u].y;
        float d2 = pv[u].z - gv[u].z;
        float d3 = (pv[u].w - gv[u].w) * wsel;   // channel 7 masked on odd lanes
        acc += d0*d0 + d1*d1 + d2*d2 + d3*d3;
    }

    // Warp reduction
    #pragma unroll
    for (int off = 16; off > 0; off >>= 1)
        acc += __shfl_xor_sync(0xFFFFFFFFu, acc, off);

    // Cross-warp reduction via shared memory
    __shared__ float warp_sums[THREADS / 32];
    const int lane = threadIdx.x & 31;
    const int wid  = threadIdx.x >> 5;
    if (lane == 0) warp_sums[wid] = acc;
    __syncthreads();

    if (wid == 0) {
        float v = (lane < THREADS / 32) ? warp_sums[lane] : 0.0f;
        #pragma unroll
        for (int off = 4; off > 0; off >>= 1)
            v += __shfl_xor_sync(0xFFFFFFFFu, v, off);

        // Publish partial (plain store), then release-ticket (orders the
        // store at gpu scope without an L1-flushing fence).
        unsigned int ticket = 0;
        if (lane == 0) {
            g_partials[b * SPLIT + s] = v;
            ticket = atom_add_release_gpu(&g_count[b], 1u);
        }
        ticket = __shfl_sync(0xFFFFFFFFu, ticket, 0);

        // Last block for this batch row reduces all 32 partials.
        if (ticket == SPLIT - 1) {
            float r = ld_acquire_gpu(&g_partials[b * SPLIT + lane]);
            #pragma unroll
            for (int off = 16; off > 0; off >>= 1)
                r += __shfl_xor_sync(0xFFFFFFFFu, r, off);
            if (lane == 0) {
                out[b] = r;
                g_count[b] = 0;                      // reset for next graph replay
            }
        }
    }
}

extern "C" void kernel_launch(void* const* d_in, const int* in_sizes, int n_in,
                              void* d_out, int out_size) {
    const float* pred = (const float*)d_in[0];
    const float* gt   = (const float*)d_in[1];
    float* out        = (float*)d_out;

    dim3 grid(B_DIM, SPLIT);
    label_loss_kernel<<<grid, THREADS>>>(pred, gt, out);
}